// round 2
// baseline (speedup 1.0000x reference)
#include <cuda_runtime.h>
#include <math.h>

#define SEQ    8192
#define BATCH  4
#define DREC   1024
#define NCHUNK 128
#define CHUNKSZ 64
#define MROWS  (BATCH * SEQ)          // 32768

// ---------------- scratch (static device arrays; no runtime allocation) ----------------
__device__ float g_aiv[(size_t)MROWS * 3 * DREC];   // 384 MB
__device__ float g_a  [(size_t)MROWS * DREC];       // 128 MB  decay a
__device__ float g_s  [(size_t)MROWS * DREC];       // 128 MB  input signal
__device__ float g_h  [(size_t)MROWS * DREC];       // 128 MB  scan output
__device__ float g_ctd[BATCH * NCHUNK * DREC];      // chunk_total_decay
__device__ float g_cfs[BATCH * NCHUNK * DREC];      // chunk_final_state
__device__ float g_inc[BATCH * NCHUNK * DREC];      // incoming_state per chunk

// ---------------- SGEMM: C[M,N] = A[M,K] @ B[K,N] (+bias), all row-major ----------------
// BM=128, BN=128, BK=16, 256 threads, 8x8 per thread. M%128==0, N%128==0, K%16==0 assumed.
__global__ __launch_bounds__(256) void sgemm128(
    const float* __restrict__ A, const float* __restrict__ B,
    const float* __restrict__ bias, float* __restrict__ C,
    int M, int N, int K)
{
    __shared__ float As[16][128];   // [k][m]  (A transposed into smem)
    __shared__ float Bs[16][128];   // [k][n]

    const int tid = threadIdx.x;
    const int tx  = tid & 15;       // 0..15  (n direction)
    const int ty  = tid >> 4;       // 0..15  (m direction)
    const size_t aBase = (size_t)blockIdx.y * 128 * (size_t)K;
    const int    nBase = blockIdx.x * 128;

    float acc[8][8];
    #pragma unroll
    for (int i = 0; i < 8; i++)
        #pragma unroll
        for (int j = 0; j < 8; j++) acc[i][j] = 0.f;

    for (int k0 = 0; k0 < K; k0 += 16) {
        #pragma unroll
        for (int l = 0; l < 2; l++) {
            int lin  = tid + l * 256;                 // 0..511
            int arow = lin >> 2;                      // 0..127
            int ac4  = (lin & 3) << 2;                // 0,4,8,12
            float4 av = *reinterpret_cast<const float4*>(
                A + aBase + (size_t)arow * K + (k0 + ac4));
            As[ac4 + 0][arow] = av.x;
            As[ac4 + 1][arow] = av.y;
            As[ac4 + 2][arow] = av.z;
            As[ac4 + 3][arow] = av.w;

            int brow = lin >> 5;                      // 0..15
            int bc4  = (lin & 31) << 2;               // 0..124
            float4 bv = *reinterpret_cast<const float4*>(
                B + (size_t)(k0 + brow) * N + (nBase + bc4));
            *reinterpret_cast<float4*>(&Bs[brow][bc4]) = bv;
        }
        __syncthreads();

        #pragma unroll
        for (int kk = 0; kk < 16; kk++) {
            float ar[8], br[8];
            *reinterpret_cast<float4*>(&ar[0]) = *reinterpret_cast<float4*>(&As[kk][ty * 8]);
            *reinterpret_cast<float4*>(&ar[4]) = *reinterpret_cast<float4*>(&As[kk][ty * 8 + 4]);
            *reinterpret_cast<float4*>(&br[0]) = *reinterpret_cast<float4*>(&Bs[kk][tx * 8]);
            *reinterpret_cast<float4*>(&br[4]) = *reinterpret_cast<float4*>(&Bs[kk][tx * 8 + 4]);
            #pragma unroll
            for (int i = 0; i < 8; i++)
                #pragma unroll
                for (int j = 0; j < 8; j++)
                    acc[i][j] += ar[i] * br[j];
        }
        __syncthreads();
    }

    #pragma unroll
    for (int i = 0; i < 8; i++) {
        size_t row = (size_t)blockIdx.y * 128 + ty * 8 + i;
        float* crow = C + row * (size_t)N + nBase + tx * 8;
        #pragma unroll
        for (int j = 0; j < 8; j++) {
            float v = acc[i][j];
            if (bias) v += bias[nBase + tx * 8 + j];
            crow[j] = v;
        }
    }
}

// ---------------- activation: a = sigmoid(a_proj + bias_d), s = sqrt(max(1-a^2,1e-8))*(sigmoid(i)*v) ----
__global__ __launch_bounds__(256) void act_kernel(const float* __restrict__ decay_bias)
{
    size_t idx = (size_t)blockIdx.x * 256 + threadIdx.x;   // 0 .. MROWS*DREC-1
    int    d   = (int)(idx & (DREC - 1));
    size_t row = idx >> 10;
    const float* base = g_aiv + row * (3 * DREC);
    float ap = base[d];
    float ip = base[DREC + d];
    float v  = base[2 * DREC + d];
    float a  = 1.f / (1.f + expf(-(ap + decay_bias[d])));
    float ig = 1.f / (1.f + expf(-ip));
    float s  = sqrtf(fmaxf(1.f - a * a, 1e-8f)) * (ig * v);
    g_a[idx] = a;
    g_s[idx] = s;
}

// ---------------- phase 1: per-chunk stats, replicating exp(cumsum(log)) + clamps exactly ----
__global__ __launch_bounds__(256) void chunk_stats_kernel()
{
    int d = blockIdx.x * 256 + threadIdx.x;   // 0..1023
    int c = blockIdx.y;                        // chunk
    int b = blockIdx.z;                        // batch
    size_t base = ((size_t)b * SEQ + (size_t)c * CHUNKSZ) * DREC + d;

    float cl = 0.f;      // cumsum of log
    float cd = 1.f;      // cum_decay = exp(cl)
    float ws = 0.f;      // cumsum of weighted
    #pragma unroll 4
    for (int j = 0; j < CHUNKSZ; j++) {
        float a = g_a[base + (size_t)j * DREC];
        float s = g_s[base + (size_t)j * DREC];
        cl += logf(fmaxf(a, 1e-10f));
        cd  = expf(cl);
        ws += s / fmaxf(cd, 1e-10f);
    }
    int o = (b * NCHUNK + c) * DREC + d;
    g_ctd[o] = cd;          // chunk_total_decay
    g_cfs[o] = cd * ws;     // chunk_final_state (= intra_state at last pos)
}

// ---------------- phase 2: serial inter-chunk scan per (b,d) ----------------
__global__ __launch_bounds__(256) void interchunk_kernel()
{
    int d = blockIdx.x * 256 + threadIdx.x;   // 0..1023
    int b = blockIdx.y;
    float cl  = 0.f;   // cum_log_chunk
    float ccd = 1.f;   // cum_chunk_decay (incoming for chunk 0 is 1*0)
    float cw  = 0.f;   // cum_weighted_chunk
    for (int c = 0; c < NCHUNK; c++) {
        int o = (b * NCHUNK + c) * DREC + d;
        g_inc[o] = ccd * cw;                      // incoming_state for this chunk
        cl += logf(fmaxf(g_ctd[o], 1e-10f));
        ccd = expf(cl);
        cw += g_cfs[o] / fmaxf(ccd, 1e-10f);
    }
}

// ---------------- phase 3: recompute intra-state + carried state, write h ----------------
__global__ __launch_bounds__(256) void states_kernel()
{
    int d = blockIdx.x * 256 + threadIdx.x;
    int c = blockIdx.y;
    int b = blockIdx.z;
    size_t base = ((size_t)b * SEQ + (size_t)c * CHUNKSZ) * DREC + d;
    float inc = g_inc[(b * NCHUNK + c) * DREC + d];

    float cl = 0.f, ws = 0.f;
    #pragma unroll 4
    for (int j = 0; j < CHUNKSZ; j++) {
        size_t idx = base + (size_t)j * DREC;
        float a = g_a[idx];
        float s = g_s[idx];
        cl += logf(fmaxf(a, 1e-10f));
        float cd = expf(cl);
        ws += s / fmaxf(cd, 1e-10f);
        g_h[idx] = cd * ws + cd * inc;   // intra_state + cross_contrib
    }
}

// ---------------- launcher ----------------
extern "C" void kernel_launch(void* const* d_in, const int* in_sizes, int n_in,
                              void* d_out, int out_size)
{
    const float* x          = (const float*)d_in[0];   // (4,8192,1024)
    const float* W_aiv      = (const float*)d_in[1];   // (1024,3072)
    const float* decay_bias = (const float*)d_in[2];   // (1024,)
    const float* W_mix      = (const float*)d_in[3];   // (1024,1024)
    const float* b_mix      = (const float*)d_in[4];   // (1024,)
    float*       out        = (float*)d_out;           // (4,8192,1024)

    float *aiv_p = nullptr, *h_p = nullptr;
    cudaGetSymbolAddress((void**)&aiv_p, g_aiv);
    cudaGetSymbolAddress((void**)&h_p,   g_h);

    // 1) aiv = x @ W_aiv
    sgemm128<<<dim3(3072 / 128, MROWS / 128), 256>>>(x, W_aiv, nullptr, aiv_p,
                                                     MROWS, 3 * DREC, 1024);
    // 2) gates + input signal
    act_kernel<<<(MROWS * DREC) / 256, 256>>>(decay_bias);
    // 3) chunked scan (exact reference numerics)
    chunk_stats_kernel<<<dim3(DREC / 256, NCHUNK, BATCH), 256>>>();
    interchunk_kernel<<<dim3(DREC / 256, BATCH), 256>>>();
    states_kernel<<<dim3(DREC / 256, NCHUNK, BATCH), 256>>>();
    // 4) out = h @ W_mix + b_mix
    sgemm128<<<dim3(DREC / 128, MROWS / 128), 256>>>(h_p, W_mix, b_mix, out,
                                                     MROWS, DREC, 1024);
}

// round 5
// speedup vs baseline: 4.7078x; 4.7078x over previous
#include <cuda_runtime.h>
#include <cuda_bf16.h>
#include <math.h>
#include <cstdint>

#define SEQ     8192
#define BATCH   4
#define DREC    1024
#define NCHUNK  128
#define CHUNKSZ 64
#define MROWS   (BATCH * SEQ)      // 32768
#define KDIM    1024

// tcgen05 is arch-SPECIFIC (sm_103a); the harness also runs a plain compute_103
// PTX pass where those instructions are illegal. Guard them; the fallback path
// is dead code at runtime (sm_103a SASS is loaded on GB300).
#if defined(__CUDA_ARCH_FEAT_SM103_ALL) || defined(__CUDA_ARCH_FEAT_SM100_ALL) || defined(__CUDA_ARCH_FEAT_SM101_ALL)
#define TC_OK 1
#else
#define TC_OK 0
#endif

// ---------------- scratch ----------------
__device__ float g_aiv[(size_t)MROWS * 3 * DREC];
__device__ float g_a  [(size_t)MROWS * DREC];
__device__ float g_s  [(size_t)MROWS * DREC];
__device__ float g_h  [(size_t)MROWS * DREC];
__device__ float g_ctd[BATCH * NCHUNK * DREC];
__device__ float g_cfs[BATCH * NCHUNK * DREC];
__device__ float g_inc[BATCH * NCHUNK * DREC];
__device__ __nv_bfloat16 g_w1th[3072 * 1024];   // W_aiv^T hi  [N,K]
__device__ __nv_bfloat16 g_w1tl[3072 * 1024];   // W_aiv^T lo
__device__ __nv_bfloat16 g_w2th[1024 * 1024];   // W_mix^T hi
__device__ __nv_bfloat16 g_w2tl[1024 * 1024];   // W_mix^T lo

// ---------------- PTX helpers ----------------
__device__ __forceinline__ uint32_t smem_to_u32(const void* p) {
    uint32_t a;
    asm("{ .reg .u64 t; cvta.to.shared.u64 t, %1; cvt.u32.u64 %0, t; }" : "=r"(a) : "l"(p));
    return a;
}
__device__ __forceinline__ uint32_t elect_one_pred() {
    uint32_t p;
    asm volatile("{\n\t.reg .pred p;\n\telect.sync _|p, 0xFFFFFFFF;\n\tselp.b32 %0, 1, 0, p;\n\t}" : "=r"(p));
    return p;
}
#define MBARRIER_INIT(addr, cnt) \
    asm volatile("mbarrier.init.shared.b64 [%0], %1;" :: "r"((uint32_t)(addr)), "r"((uint32_t)(cnt)) : "memory")
#define MBARRIER_INVAL(addr) \
    asm volatile("mbarrier.inval.shared.b64 [%0];" :: "r"((uint32_t)(addr)) : "memory")
#define MBARRIER_WAIT_PARITY(mbar_smem_addr, phase_parity) do { \
    uint32_t _mbar = (uint32_t)(mbar_smem_addr); \
    uint32_t _parity = (uint32_t)(phase_parity); \
    uint32_t _done; \
    asm volatile("{\n\t.reg .pred p;\n\t" \
        "mbarrier.try_wait.parity.acquire.cta.shared::cta.b64 p, [%1], %2;\n\t" \
        "selp.b32 %0, 1, 0, p;\n\t}" \
        : "=r"(_done) : "r"(_mbar), "r"(_parity) : "memory"); \
    if (!_done) { \
        asm volatile("{\n\t.reg .pred P1;\n\t" \
            "WAIT_LOOP_%=:\n\t" \
            "mbarrier.try_wait.parity.acquire.cta.shared::cta.b64 P1, [%0], %1, 0x989680;\n\t" \
            "@P1 bra.uni WAIT_DONE_%=;\n\t" \
            "bra.uni WAIT_LOOP_%=;\n\t" \
            "WAIT_DONE_%=:\n\t}" \
            :: "r"(_mbar), "r"(_parity) : "memory"); \
    } \
} while(0)

#if TC_OK
#define TCGEN05_ALLOC(smem_result_addr, nCols) \
    asm volatile("tcgen05.alloc.cta_group::1.sync.aligned.shared::cta.b32 [%0], %1;" \
        :: "r"((uint32_t)(smem_result_addr)), "r"((uint32_t)(nCols)) : "memory")
#define TCGEN05_DEALLOC(tmem_addr, nCols) \
    asm volatile("tcgen05.dealloc.cta_group::1.sync.aligned.b32 %0, %1;" :: "r"(tmem_addr), "r"((uint32_t)(nCols)))
#define TCGEN05_RELINQUISH() \
    asm volatile("tcgen05.relinquish_alloc_permit.cta_group::1.sync.aligned;")
#define TCGEN05_COMMIT(mbar_smem_addr) \
    asm volatile("tcgen05.commit.cta_group::1.mbarrier::arrive::one.shared::cluster.b64 [%0];" \
        :: "r"((uint32_t)(mbar_smem_addr)) : "memory")
#define TCGEN05_FENCE_AFTER()  asm volatile("tcgen05.fence::after_thread_sync;" ::: "memory")
#define TCGEN05_WAIT_LD()      asm volatile("tcgen05.wait::ld.sync.aligned;" ::: "memory")
#define TCGEN05_LD_32X32B_X32(r, tmem_addr) \
    asm volatile("tcgen05.ld.sync.aligned.32x32b.x32.b32 " \
        "{%0, %1, %2, %3, %4, %5, %6, %7, %8, %9, %10, %11, %12, %13, %14, %15, " \
        "%16, %17, %18, %19, %20, %21, %22, %23, %24, %25, %26, %27, %28, %29, %30, %31}, [%32];" \
        : "=r"((r)[0]),  "=r"((r)[1]),  "=r"((r)[2]),  "=r"((r)[3]), \
          "=r"((r)[4]),  "=r"((r)[5]),  "=r"((r)[6]),  "=r"((r)[7]), \
          "=r"((r)[8]),  "=r"((r)[9]),  "=r"((r)[10]), "=r"((r)[11]), \
          "=r"((r)[12]), "=r"((r)[13]), "=r"((r)[14]), "=r"((r)[15]), \
          "=r"((r)[16]), "=r"((r)[17]), "=r"((r)[18]), "=r"((r)[19]), \
          "=r"((r)[20]), "=r"((r)[21]), "=r"((r)[22]), "=r"((r)[23]), \
          "=r"((r)[24]), "=r"((r)[25]), "=r"((r)[26]), "=r"((r)[27]), \
          "=r"((r)[28]), "=r"((r)[29]), "=r"((r)[30]), "=r"((r)[31]) \
        : "r"(tmem_addr))
__device__ __forceinline__ void mma_f16_ss(uint32_t d, uint64_t a, uint64_t b,
                                           uint32_t idesc, uint32_t en) {
    asm volatile(
        "{\n\t.reg .pred p;\n\tsetp.ne.u32 p, %5, 0;\n\t"
        "tcgen05.mma.cta_group::1.kind::f16 [%0], %1, %2, %3, {%4, %4, %4, %4}, p;\n\t}"
        :: "r"(d), "l"(a), "l"(b), "r"(idesc), "r"(0u), "r"(en) : "memory");
}
#else
// Dead fallback for the generic compute_103 PTX pass (never executed on GB300).
#define TCGEN05_ALLOC(a, n)      ((void)0)
#define TCGEN05_DEALLOC(t, n)    ((void)0)
#define TCGEN05_RELINQUISH()     ((void)0)
#define TCGEN05_COMMIT(m)        ((void)0)
#define TCGEN05_FENCE_AFTER()    ((void)0)
#define TCGEN05_WAIT_LD()        ((void)0)
#define TCGEN05_LD_32X32B_X32(r, t) do { _Pragma("unroll") \
    for (int _i = 0; _i < 32; _i++) (r)[_i] = 0u; (void)(t); } while(0)
__device__ __forceinline__ void mma_f16_ss(uint32_t, uint64_t, uint64_t, uint32_t, uint32_t) {}
#endif

#define SMEM_SWIZZLE_128B(off) ((off) ^ (((off) >> 3) & 0x70))
static constexpr uint64_t SMEM_DESC_BASE_SW128 =
    (uint64_t(2) << 61) | (uint64_t(1) << 46) | (uint64_t(64) << 32) | (uint64_t(1) << 16);
#define MAKE_SMEM_DESC(base_addr) (SMEM_DESC_BASE_SW128 | ((uint64_t)((base_addr) >> 4) & 0x3FFF))

// ---------------- weight transpose + bf16 hi/lo split: W[K,N] -> T[N,K] ----------------
__global__ __launch_bounds__(256) void wconv_kernel(
    const float* __restrict__ W, __nv_bfloat16* __restrict__ Th,
    __nv_bfloat16* __restrict__ Tl, int K, int N)
{
    __shared__ float t[32][33];
    int n0 = blockIdx.x * 32, k0 = blockIdx.y * 32;
    int tx = threadIdx.x & 31, ty = threadIdx.x >> 5;   // 32 x 8
    #pragma unroll
    for (int dy = 0; dy < 32; dy += 8)
        t[ty + dy][tx] = W[(size_t)(k0 + ty + dy) * N + n0 + tx];
    __syncthreads();
    #pragma unroll
    for (int dy = 0; dy < 32; dy += 8) {
        float v = t[tx][ty + dy];
        __nv_bfloat16 h = __float2bfloat16(v);
        size_t o = (size_t)(n0 + ty + dy) * K + k0 + tx;
        Th[o] = h;
        Tl[o] = __float2bfloat16(v - __bfloat162float(h));
    }
}

// ---------------- tcgen05 bf16-split GEMM: C[M,Ntot] = A @ T^T (+bias) ----------------
#define BM 128
#define BN 256
#define KC 64
#define SM_AH 0
#define SM_AL 16384
#define SM_BH 32768
#define SM_BL 65536
#define STAGE_BYTES 98304
#define SM_TILES 1024
#define GEMM_SMEM (SM_TILES + 2 * STAGE_BYTES)   // 197632

__global__ __launch_bounds__(256, 1) void tc_gemm(
    const float* __restrict__ A,
    const __nv_bfloat16* __restrict__ Bh,
    const __nv_bfloat16* __restrict__ Bl,
    const float* __restrict__ bias,
    float* __restrict__ C, int Ntot)
{
    extern __shared__ char smem[];
    const uint32_t sb = smem_to_u32(smem);
    const int tid = threadIdx.x, wid = tid >> 5, lid = tid & 31;
    const int mBase = blockIdx.y * BM;
    const int nBase = blockIdx.x * BN;

    if (tid == 0) { MBARRIER_INIT(sb + 8, 1); MBARRIER_INIT(sb + 16, 1); }
    if (wid == 0) { TCGEN05_ALLOC(sb + 0, 256); TCGEN05_RELINQUISH(); }
    __syncthreads();
    uint32_t tmem;
    asm volatile("ld.shared.b32 %0, [%1];" : "=r"(tmem) : "r"(sb));

    const uint32_t idesc = (1u << 4) | (1u << 7) | (1u << 10)
                         | ((BN / 8) << 17) | ((BM / 16) << 24);

    int ph0 = 0, ph1 = 0;
    for (int kt = 0; kt < KDIM / KC; kt++) {
        const int st = kt & 1;
        const uint32_t stBase = SM_TILES + st * STAGE_BYTES;
        if (kt >= 2) {
            if (st == 0) { MBARRIER_WAIT_PARITY(sb + 8,  ph0); ph0 ^= 1; }
            else         { MBARRIER_WAIT_PARITY(sb + 16, ph1); ph1 ^= 1; }
        }
        const int k0 = kt * KC;

        // A tile: 128 rows x 64 fp32 -> hi/lo bf16 smem (SW128)
        const float* Ab = A + (size_t)mBase * KDIM + k0;
        #pragma unroll
        for (int l = 0; l < 8; l++) {
            int i = tid + l * 256;            // 0..2047
            int row = i >> 4, c = i & 15;     // c: 4-float chunk
            float4 v = *(const float4*)(Ab + (size_t)row * KDIM + c * 4);
            __nv_bfloat162 h01 = __floats2bfloat162_rn(v.x, v.y);
            __nv_bfloat162 h23 = __floats2bfloat162_rn(v.z, v.w);
            __nv_bfloat162 l01 = __floats2bfloat162_rn(v.x - __bfloat162float(h01.x),
                                                       v.y - __bfloat162float(h01.y));
            __nv_bfloat162 l23 = __floats2bfloat162_rn(v.z - __bfloat162float(h23.x),
                                                       v.w - __bfloat162float(h23.y));
            uint32_t sw = SMEM_SWIZZLE_128B((uint32_t)(row * 128 + c * 8));
            uint2 hv = make_uint2(*(uint32_t*)&h01, *(uint32_t*)&h23);
            uint2 lv = make_uint2(*(uint32_t*)&l01, *(uint32_t*)&l23);
            *(uint2*)(smem + stBase + SM_AH + sw) = hv;
            *(uint2*)(smem + stBase + SM_AL + sw) = lv;
        }
        // B tiles: 256 rows x 64 bf16 (already [N,K])
        const __nv_bfloat16* Bhb = Bh + (size_t)nBase * KDIM + k0;
        const __nv_bfloat16* Blb = Bl + (size_t)nBase * KDIM + k0;
        #pragma unroll
        for (int l = 0; l < 8; l++) {
            int i = tid + l * 256;            // 0..2047
            int row = i >> 3, c = i & 7;      // c: 8-bf16 chunk
            uint32_t sw = SMEM_SWIZZLE_128B((uint32_t)(row * 128 + c * 16));
            *(uint4*)(smem + stBase + SM_BH + sw) =
                *(const uint4*)(Bhb + (size_t)row * KDIM + c * 8);
            *(uint4*)(smem + stBase + SM_BL + sw) =
                *(const uint4*)(Blb + (size_t)row * KDIM + c * 8);
        }
        __syncthreads();

        if (wid == 0 && elect_one_pred()) {
            asm volatile("fence.proxy.async.shared::cta;" ::: "memory");
            uint64_t dAh = MAKE_SMEM_DESC(sb + stBase + SM_AH);
            uint64_t dAl = MAKE_SMEM_DESC(sb + stBase + SM_AL);
            uint64_t dBh = MAKE_SMEM_DESC(sb + stBase + SM_BH);
            uint64_t dBl = MAKE_SMEM_DESC(sb + stBase + SM_BL);
            #pragma unroll
            for (int ks = 0; ks < 4; ks++) {
                uint32_t acc0 = (kt == 0 && ks == 0) ? 0u : 1u;
                mma_f16_ss(tmem, dAh + ks * 2, dBh + ks * 2, idesc, acc0);
                mma_f16_ss(tmem, dAh + ks * 2, dBl + ks * 2, idesc, 1u);
                mma_f16_ss(tmem, dAl + ks * 2, dBh + ks * 2, idesc, 1u);
            }
            TCGEN05_COMMIT(sb + 8 + st * 8);
        }
    }
    MBARRIER_WAIT_PARITY(sb + 8,  ph0);
    MBARRIER_WAIT_PARITY(sb + 16, ph1);
    TCGEN05_FENCE_AFTER();

    // epilogue: warps 0-3 read D rows, write fp32 (+bias)
    if (wid < 4) {
        int row = mBase + wid * 32 + lid;
        float* crow = C + (size_t)row * Ntot + nBase;
        for (int nb = 0; nb < BN; nb += 32) {
            uint32_t r[32];
            TCGEN05_LD_32X32B_X32(r, tmem + nb);
            TCGEN05_WAIT_LD();
            #pragma unroll
            for (int j = 0; j < 32; j += 4) {
                float4 v;
                v.x = __uint_as_float(r[j + 0]);
                v.y = __uint_as_float(r[j + 1]);
                v.z = __uint_as_float(r[j + 2]);
                v.w = __uint_as_float(r[j + 3]);
                if (bias) {
                    const float* bp = bias + nBase + nb + j;
                    v.x += bp[0]; v.y += bp[1]; v.z += bp[2]; v.w += bp[3];
                }
                *(float4*)(crow + nb + j) = v;
            }
        }
    }
    __syncthreads();
    if (tid == 0) { MBARRIER_INVAL(sb + 8); MBARRIER_INVAL(sb + 16); }
    if (wid == 0) { TCGEN05_DEALLOC(tmem, 256); }
}

// ---------------- activation ----------------
__global__ __launch_bounds__(256) void act_kernel(const float* __restrict__ decay_bias)
{
    size_t idx = (size_t)blockIdx.x * 256 + threadIdx.x;
    int    d   = (int)(idx & (DREC - 1));
    size_t row = idx >> 10;
    const float* base = g_aiv + row * (3 * DREC);
    float ap = base[d];
    float ip = base[DREC + d];
    float v  = base[2 * DREC + d];
    float a  = 1.f / (1.f + expf(-(ap + decay_bias[d])));
    float ig = 1.f / (1.f + expf(-ip));
    float s  = sqrtf(fmaxf(1.f - a * a, 1e-8f)) * (ig * v);
    g_a[idx] = a;
    g_s[idx] = s;
}

// ---------------- phase 1: per-chunk stats (exact reference numerics) ----------------
__global__ __launch_bounds__(256) void chunk_stats_kernel()
{
    int d = blockIdx.x * 256 + threadIdx.x;
    int c = blockIdx.y;
    int b = blockIdx.z;
    size_t base = ((size_t)b * SEQ + (size_t)c * CHUNKSZ) * DREC + d;

    float cl = 0.f, cd = 1.f, ws = 0.f;
    #pragma unroll 4
    for (int j = 0; j < CHUNKSZ; j++) {
        float a = g_a[base + (size_t)j * DREC];
        float s = g_s[base + (size_t)j * DREC];
        cl += logf(fmaxf(a, 1e-10f));
        cd  = expf(cl);
        ws += s / fmaxf(cd, 1e-10f);
    }
    int o = (b * NCHUNK + c) * DREC + d;
    g_ctd[o] = cd;
    g_cfs[o] = cd * ws;
}

// ---------------- phase 2: serial inter-chunk scan ----------------
__global__ __launch_bounds__(256) void interchunk_kernel()
{
    int d = blockIdx.x * 256 + threadIdx.x;
    int b = blockIdx.y;
    float cl = 0.f, ccd = 1.f, cw = 0.f;
    for (int c = 0; c < NCHUNK; c++) {
        int o = (b * NCHUNK + c) * DREC + d;
        g_inc[o] = ccd * cw;
        cl += logf(fmaxf(g_ctd[o], 1e-10f));
        ccd = expf(cl);
        cw += g_cfs[o] / fmaxf(ccd, 1e-10f);
    }
}

// ---------------- phase 3: final states ----------------
__global__ __launch_bounds__(256) void states_kernel()
{
    int d = blockIdx.x * 256 + threadIdx.x;
    int c = blockIdx.y;
    int b = blockIdx.z;
    size_t base = ((size_t)b * SEQ + (size_t)c * CHUNKSZ) * DREC + d;
    float inc = g_inc[(b * NCHUNK + c) * DREC + d];

    float cl = 0.f, ws = 0.f;
    #pragma unroll 4
    for (int j = 0; j < CHUNKSZ; j++) {
        size_t idx = base + (size_t)j * DREC;
        float a = g_a[idx];
        float s = g_s[idx];
        cl += logf(fmaxf(a, 1e-10f));
        float cd = expf(cl);
        ws += s / fmaxf(cd, 1e-10f);
        g_h[idx] = cd * ws + cd * inc;
    }
}

// ---------------- launcher ----------------
extern "C" void kernel_launch(void* const* d_in, const int* in_sizes, int n_in,
                              void* d_out, int out_size)
{
    const float* x          = (const float*)d_in[0];
    const float* W_aiv      = (const float*)d_in[1];
    const float* decay_bias = (const float*)d_in[2];
    const float* W_mix      = (const float*)d_in[3];
    const float* b_mix      = (const float*)d_in[4];
    float*       out        = (float*)d_out;

    float *aiv_p, *h_p;
    __nv_bfloat16 *w1th, *w1tl, *w2th, *w2tl;
    cudaGetSymbolAddress((void**)&aiv_p, g_aiv);
    cudaGetSymbolAddress((void**)&h_p,   g_h);
    cudaGetSymbolAddress((void**)&w1th,  g_w1th);
    cudaGetSymbolAddress((void**)&w1tl,  g_w1tl);
    cudaGetSymbolAddress((void**)&w2th,  g_w2th);
    cudaGetSymbolAddress((void**)&w2tl,  g_w2tl);

    cudaFuncSetAttribute(tc_gemm, cudaFuncAttributeMaxDynamicSharedMemorySize, GEMM_SMEM);

    // weight conversion (transpose + hi/lo split)
    wconv_kernel<<<dim3(3072 / 32, 1024 / 32), 256>>>(W_aiv, w1th, w1tl, 1024, 3072);
    wconv_kernel<<<dim3(1024 / 32, 1024 / 32), 256>>>(W_mix, w2th, w2tl, 1024, 1024);

    // 1) aiv = x @ W_aiv  (tensor cores)
    tc_gemm<<<dim3(3072 / BN, MROWS / BM), 256, GEMM_SMEM>>>(x, w1th, w1tl, nullptr, aiv_p, 3072);
    // 2) gates
    act_kernel<<<(MROWS * DREC) / 256, 256>>>(decay_bias);
    // 3) chunked scan
    chunk_stats_kernel<<<dim3(DREC / 256, NCHUNK, BATCH), 256>>>();
    interchunk_kernel<<<dim3(DREC / 256, BATCH), 256>>>();
    states_kernel<<<dim3(DREC / 256, NCHUNK, BATCH), 256>>>();
    // 4) out = h @ W_mix + b_mix  (tensor cores)
    tc_gemm<<<dim3(1024 / BN, MROWS / BM), 256, GEMM_SMEM>>>(h_p, w2th, w2tl, b_mix, out, 1024);
}

// round 6
// speedup vs baseline: 5.2286x; 1.1106x over previous
#include <cuda_runtime.h>
#include <cuda_bf16.h>
#include <math.h>
#include <cstdint>

#define SEQ     8192
#define BATCH   4
#define DREC    1024
#define NCHUNK  128
#define CHUNKSZ 64
#define MROWS   (BATCH * SEQ)      // 32768
#define KDIM    1024

#if defined(__CUDA_ARCH_FEAT_SM103_ALL) || defined(__CUDA_ARCH_FEAT_SM100_ALL) || defined(__CUDA_ARCH_FEAT_SM101_ALL)
#define TC_OK 1
#else
#define TC_OK 0
#endif

// ---------------- scratch ----------------
__device__ float g_aiv[(size_t)MROWS * 3 * DREC];
__device__ float g_a  [(size_t)MROWS * DREC];
__device__ float g_s  [(size_t)MROWS * DREC];
__device__ float g_ctd[BATCH * NCHUNK * DREC];
__device__ float g_cfs[BATCH * NCHUNK * DREC];
__device__ float g_inc[BATCH * NCHUNK * DREC];
__device__ __nv_bfloat16 g_xh[(size_t)MROWS * KDIM];   // x hi
__device__ __nv_bfloat16 g_xl[(size_t)MROWS * KDIM];   // x lo
__device__ __nv_bfloat16 g_hh[(size_t)MROWS * DREC];   // h hi
__device__ __nv_bfloat16 g_hl[(size_t)MROWS * DREC];   // h lo
__device__ __nv_bfloat16 g_w1th[3072 * 1024];
__device__ __nv_bfloat16 g_w1tl[3072 * 1024];
__device__ __nv_bfloat16 g_w2th[1024 * 1024];
__device__ __nv_bfloat16 g_w2tl[1024 * 1024];

// ---------------- PTX helpers ----------------
__device__ __forceinline__ uint32_t smem_to_u32(const void* p) {
    uint32_t a;
    asm("{ .reg .u64 t; cvta.to.shared.u64 t, %1; cvt.u32.u64 %0, t; }" : "=r"(a) : "l"(p));
    return a;
}
__device__ __forceinline__ uint32_t elect_one_pred() {
    uint32_t p;
    asm volatile("{\n\t.reg .pred p;\n\telect.sync _|p, 0xFFFFFFFF;\n\tselp.b32 %0, 1, 0, p;\n\t}" : "=r"(p));
    return p;
}
#define MBARRIER_INIT(addr, cnt) \
    asm volatile("mbarrier.init.shared.b64 [%0], %1;" :: "r"((uint32_t)(addr)), "r"((uint32_t)(cnt)) : "memory")
#define MBARRIER_INVAL(addr) \
    asm volatile("mbarrier.inval.shared.b64 [%0];" :: "r"((uint32_t)(addr)) : "memory")
#define MBARRIER_WAIT_PARITY(mbar_smem_addr, phase_parity) do { \
    uint32_t _mbar = (uint32_t)(mbar_smem_addr); \
    uint32_t _parity = (uint32_t)(phase_parity); \
    uint32_t _done; \
    asm volatile("{\n\t.reg .pred p;\n\t" \
        "mbarrier.try_wait.parity.acquire.cta.shared::cta.b64 p, [%1], %2;\n\t" \
        "selp.b32 %0, 1, 0, p;\n\t}" \
        : "=r"(_done) : "r"(_mbar), "r"(_parity) : "memory"); \
    if (!_done) { \
        asm volatile("{\n\t.reg .pred P1;\n\t" \
            "WAIT_LOOP_%=:\n\t" \
            "mbarrier.try_wait.parity.acquire.cta.shared::cta.b64 P1, [%0], %1, 0x989680;\n\t" \
            "@P1 bra.uni WAIT_DONE_%=;\n\t" \
            "bra.uni WAIT_LOOP_%=;\n\t" \
            "WAIT_DONE_%=:\n\t}" \
            :: "r"(_mbar), "r"(_parity) : "memory"); \
    } \
} while(0)

// cp.async (sm_80+; legal in both PTX passes)
#define CP_ASYNC16(smem_u32, gptr) \
    asm volatile("cp.async.cg.shared.global [%0], [%1], 16;" \
        :: "r"((uint32_t)(smem_u32)), "l"(gptr) : "memory")
#define CP_ASYNC_COMMIT() asm volatile("cp.async.commit_group;" ::: "memory")
#define CP_ASYNC_WAIT(n)  asm volatile("cp.async.wait_group %0;" :: "n"(n) : "memory")

#if TC_OK
#define TCGEN05_ALLOC(smem_result_addr, nCols) \
    asm volatile("tcgen05.alloc.cta_group::1.sync.aligned.shared::cta.b32 [%0], %1;" \
        :: "r"((uint32_t)(smem_result_addr)), "r"((uint32_t)(nCols)) : "memory")
#define TCGEN05_DEALLOC(tmem_addr, nCols) \
    asm volatile("tcgen05.dealloc.cta_group::1.sync.aligned.b32 %0, %1;" :: "r"(tmem_addr), "r"((uint32_t)(nCols)))
#define TCGEN05_RELINQUISH() \
    asm volatile("tcgen05.relinquish_alloc_permit.cta_group::1.sync.aligned;")
#define TCGEN05_COMMIT(mbar_smem_addr) \
    asm volatile("tcgen05.commit.cta_group::1.mbarrier::arrive::one.shared::cluster.b64 [%0];" \
        :: "r"((uint32_t)(mbar_smem_addr)) : "memory")
#define TCGEN05_FENCE_AFTER()  asm volatile("tcgen05.fence::after_thread_sync;" ::: "memory")
#define TCGEN05_WAIT_LD()      asm volatile("tcgen05.wait::ld.sync.aligned;" ::: "memory")
#define TCGEN05_LD_32X32B_X32(r, tmem_addr) \
    asm volatile("tcgen05.ld.sync.aligned.32x32b.x32.b32 " \
        "{%0, %1, %2, %3, %4, %5, %6, %7, %8, %9, %10, %11, %12, %13, %14, %15, " \
        "%16, %17, %18, %19, %20, %21, %22, %23, %24, %25, %26, %27, %28, %29, %30, %31}, [%32];" \
        : "=r"((r)[0]),  "=r"((r)[1]),  "=r"((r)[2]),  "=r"((r)[3]), \
          "=r"((r)[4]),  "=r"((r)[5]),  "=r"((r)[6]),  "=r"((r)[7]), \
          "=r"((r)[8]),  "=r"((r)[9]),  "=r"((r)[10]), "=r"((r)[11]), \
          "=r"((r)[12]), "=r"((r)[13]), "=r"((r)[14]), "=r"((r)[15]), \
          "=r"((r)[16]), "=r"((r)[17]), "=r"((r)[18]), "=r"((r)[19]), \
          "=r"((r)[20]), "=r"((r)[21]), "=r"((r)[22]), "=r"((r)[23]), \
          "=r"((r)[24]), "=r"((r)[25]), "=r"((r)[26]), "=r"((r)[27]), \
          "=r"((r)[28]), "=r"((r)[29]), "=r"((r)[30]), "=r"((r)[31]) \
        : "r"(tmem_addr))
__device__ __forceinline__ void mma_f16_ss(uint32_t d, uint64_t a, uint64_t b,
                                           uint32_t idesc, uint32_t en) {
    asm volatile(
        "{\n\t.reg .pred p;\n\tsetp.ne.u32 p, %5, 0;\n\t"
        "tcgen05.mma.cta_group::1.kind::f16 [%0], %1, %2, %3, {%4, %4, %4, %4}, p;\n\t}"
        :: "r"(d), "l"(a), "l"(b), "r"(idesc), "r"(0u), "r"(en) : "memory");
}
#else
#define TCGEN05_ALLOC(a, n)      ((void)0)
#define TCGEN05_DEALLOC(t, n)    ((void)0)
#define TCGEN05_RELINQUISH()     ((void)0)
#define TCGEN05_COMMIT(m)        ((void)0)
#define TCGEN05_FENCE_AFTER()    ((void)0)
#define TCGEN05_WAIT_LD()        ((void)0)
#define TCGEN05_LD_32X32B_X32(r, t) do { _Pragma("unroll") \
    for (int _i = 0; _i < 32; _i++) (r)[_i] = 0u; (void)(t); } while(0)
__device__ __forceinline__ void mma_f16_ss(uint32_t, uint64_t, uint64_t, uint32_t, uint32_t) {}
#endif

#define SMEM_SWIZZLE_128B(off) ((off) ^ (((off) >> 3) & 0x70))
static constexpr uint64_t SMEM_DESC_BASE_SW128 =
    (uint64_t(2) << 61) | (uint64_t(1) << 46) | (uint64_t(64) << 32) | (uint64_t(1) << 16);
#define MAKE_SMEM_DESC(base_addr) (SMEM_DESC_BASE_SW128 | ((uint64_t)((base_addr) >> 4) & 0x3FFF))

// ---------------- x -> bf16 hi/lo split ----------------
__global__ __launch_bounds__(256) void split_kernel(
    const float* __restrict__ src, __nv_bfloat16* __restrict__ hi,
    __nv_bfloat16* __restrict__ lo)
{
    size_t i = ((size_t)blockIdx.x * 256 + threadIdx.x) * 4;
    float4 v = *(const float4*)(src + i);
    __nv_bfloat162 h01 = __floats2bfloat162_rn(v.x, v.y);
    __nv_bfloat162 h23 = __floats2bfloat162_rn(v.z, v.w);
    __nv_bfloat162 l01 = __floats2bfloat162_rn(v.x - __bfloat162float(h01.x),
                                               v.y - __bfloat162float(h01.y));
    __nv_bfloat162 l23 = __floats2bfloat162_rn(v.z - __bfloat162float(h23.x),
                                               v.w - __bfloat162float(h23.y));
    *(uint2*)(hi + i) = make_uint2(*(uint32_t*)&h01, *(uint32_t*)&h23);
    *(uint2*)(lo + i) = make_uint2(*(uint32_t*)&l01, *(uint32_t*)&l23);
}

// ---------------- weight transpose + bf16 hi/lo split: W[K,N] -> T[N,K] ----------------
__global__ __launch_bounds__(256) void wconv_kernel(
    const float* __restrict__ W, __nv_bfloat16* __restrict__ Th,
    __nv_bfloat16* __restrict__ Tl, int K, int N)
{
    __shared__ float t[32][33];
    int n0 = blockIdx.x * 32, k0 = blockIdx.y * 32;
    int tx = threadIdx.x & 31, ty = threadIdx.x >> 5;
    #pragma unroll
    for (int dy = 0; dy < 32; dy += 8)
        t[ty + dy][tx] = W[(size_t)(k0 + ty + dy) * N + n0 + tx];
    __syncthreads();
    #pragma unroll
    for (int dy = 0; dy < 32; dy += 8) {
        float v = t[tx][ty + dy];
        __nv_bfloat16 h = __float2bfloat16(v);
        size_t o = (size_t)(n0 + ty + dy) * K + k0 + tx;
        Th[o] = h;
        Tl[o] = __float2bfloat16(v - __bfloat162float(h));
    }
}

// ---------------- tcgen05 bf16-split GEMM (cp.async pipelined) ----------------
#define BM 128
#define BN 256
#define KC 64
#define SM_AH 0
#define SM_AL 16384
#define SM_BH 32768
#define SM_BL 65536
#define STAGE_BYTES 98304
#define SM_TILES 1024
#define GEMM_SMEM (SM_TILES + 2 * STAGE_BYTES)   // 197632
#define NKI (KDIM / KC)                          // 16

__device__ __forceinline__ void fill_stage(
    uint32_t sb, uint32_t stBase, int tid,
    const __nv_bfloat16* __restrict__ Ahb, const __nv_bfloat16* __restrict__ Alb,
    const __nv_bfloat16* __restrict__ Bhb, const __nv_bfloat16* __restrict__ Blb)
{
    // A tiles: 128 rows x 64 bf16 (128B/row) hi+lo
    #pragma unroll
    for (int l = 0; l < 4; l++) {
        int i = tid + l * 256;            // 0..1023
        int row = i >> 3, c = i & 7;
        uint32_t sw = SMEM_SWIZZLE_128B((uint32_t)(row * 128 + c * 16));
        CP_ASYNC16(sb + stBase + SM_AH + sw, Ahb + (size_t)row * KDIM + c * 8);
        CP_ASYNC16(sb + stBase + SM_AL + sw, Alb + (size_t)row * KDIM + c * 8);
    }
    // B tiles: 256 rows x 64 bf16 hi+lo
    #pragma unroll
    for (int l = 0; l < 8; l++) {
        int i = tid + l * 256;            // 0..2047
        int row = i >> 3, c = i & 7;
        uint32_t sw = SMEM_SWIZZLE_128B((uint32_t)(row * 128 + c * 16));
        CP_ASYNC16(sb + stBase + SM_BH + sw, Bhb + (size_t)row * KDIM + c * 8);
        CP_ASYNC16(sb + stBase + SM_BL + sw, Blb + (size_t)row * KDIM + c * 8);
    }
}

__global__ __launch_bounds__(256, 1) void tc_gemm(
    const __nv_bfloat16* __restrict__ Ah, const __nv_bfloat16* __restrict__ Al,
    const __nv_bfloat16* __restrict__ Bh, const __nv_bfloat16* __restrict__ Bl,
    const float* __restrict__ bias,
    float* __restrict__ C, int Ntot)
{
    extern __shared__ char smem[];
    const uint32_t sb = smem_to_u32(smem);
    const int tid = threadIdx.x, wid = tid >> 5, lid = tid & 31;
    const int mBase = blockIdx.y * BM;
    const int nBase = blockIdx.x * BN;

    if (tid == 0) { MBARRIER_INIT(sb + 8, 1); MBARRIER_INIT(sb + 16, 1); }
    if (wid == 0) { TCGEN05_ALLOC(sb + 0, 256); TCGEN05_RELINQUISH(); }
    __syncthreads();
    uint32_t tmem;
    asm volatile("ld.shared.b32 %0, [%1];" : "=r"(tmem) : "r"(sb));

    const uint32_t idesc = (1u << 4) | (1u << 7) | (1u << 10)
                         | ((BN / 8) << 17) | ((BM / 16) << 24);

    const __nv_bfloat16* AhB = Ah + (size_t)mBase * KDIM;
    const __nv_bfloat16* AlB = Al + (size_t)mBase * KDIM;
    const __nv_bfloat16* BhB = Bh + (size_t)nBase * KDIM;
    const __nv_bfloat16* BlB = Bl + (size_t)nBase * KDIM;

    // prologue: async-fill both stages
    fill_stage(sb, SM_TILES, tid, AhB, AlB, BhB, BlB);
    CP_ASYNC_COMMIT();
    fill_stage(sb, SM_TILES + STAGE_BYTES, tid,
               AhB + KC, AlB + KC, BhB + KC, BlB + KC);
    CP_ASYNC_COMMIT();

    int ph0 = 0, ph1 = 0;
    for (int kt = 0; kt < NKI; kt++) {
        const int st = kt & 1;
        const uint32_t stBase = SM_TILES + st * STAGE_BYTES;
        if (kt == NKI - 1) CP_ASYNC_WAIT(0); else CP_ASYNC_WAIT(1);
        __syncthreads();

        if (wid == 0 && elect_one_pred()) {
            asm volatile("fence.proxy.async.shared::cta;" ::: "memory");
            uint64_t dAh = MAKE_SMEM_DESC(sb + stBase + SM_AH);
            uint64_t dAl = MAKE_SMEM_DESC(sb + stBase + SM_AL);
            uint64_t dBh = MAKE_SMEM_DESC(sb + stBase + SM_BH);
            uint64_t dBl = MAKE_SMEM_DESC(sb + stBase + SM_BL);
            #pragma unroll
            for (int ks = 0; ks < 4; ks++) {
                uint32_t acc0 = (kt == 0 && ks == 0) ? 0u : 1u;
                mma_f16_ss(tmem, dAh + ks * 2, dBh + ks * 2, idesc, acc0);
                mma_f16_ss(tmem, dAh + ks * 2, dBl + ks * 2, idesc, 1u);
                mma_f16_ss(tmem, dAl + ks * 2, dBh + ks * 2, idesc, 1u);
            }
            TCGEN05_COMMIT(sb + 8 + st * 8);
        }

        if (kt + 2 < NKI) {
            // buffer st is reusable once the MMAs just committed on it finish
            if (st == 0) { MBARRIER_WAIT_PARITY(sb + 8,  ph0); ph0 ^= 1; }
            else         { MBARRIER_WAIT_PARITY(sb + 16, ph1); ph1 ^= 1; }
            const int k2 = (kt + 2) * KC;
            fill_stage(sb, stBase, tid, AhB + k2, AlB + k2, BhB + k2, BlB + k2);
            CP_ASYNC_COMMIT();
        }
    }
    MBARRIER_WAIT_PARITY(sb + 8,  ph0);
    MBARRIER_WAIT_PARITY(sb + 16, ph1);
    TCGEN05_FENCE_AFTER();

    // epilogue: warps 0-3 read D rows, write fp32 (+bias)
    if (wid < 4) {
        int row = mBase + wid * 32 + lid;
        float* crow = C + (size_t)row * Ntot + nBase;
        for (int nb = 0; nb < BN; nb += 32) {
            uint32_t r[32];
            TCGEN05_LD_32X32B_X32(r, tmem + nb);
            TCGEN05_WAIT_LD();
            #pragma unroll
            for (int j = 0; j < 32; j += 4) {
                float4 v;
                v.x = __uint_as_float(r[j + 0]);
                v.y = __uint_as_float(r[j + 1]);
                v.z = __uint_as_float(r[j + 2]);
                v.w = __uint_as_float(r[j + 3]);
                if (bias) {
                    const float* bp = bias + nBase + nb + j;
                    v.x += bp[0]; v.y += bp[1]; v.z += bp[2]; v.w += bp[3];
                }
                *(float4*)(crow + nb + j) = v;
            }
        }
    }
    __syncthreads();
    if (tid == 0) { MBARRIER_INVAL(sb + 8); MBARRIER_INVAL(sb + 16); }
    if (wid == 0) { TCGEN05_DEALLOC(tmem, 256); }
}

// ---------------- activation (vectorized x4) ----------------
__global__ __launch_bounds__(256) void act_kernel(const float* __restrict__ decay_bias)
{
    size_t i4 = ((size_t)blockIdx.x * 256 + threadIdx.x) * 4;
    int    d  = (int)(i4 & (DREC - 1));
    size_t row = i4 >> 10;
    const float* base = g_aiv + row * (3 * DREC);
    float4 ap = *(const float4*)(base + d);
    float4 ip = *(const float4*)(base + DREC + d);
    float4 vv = *(const float4*)(base + 2 * DREC + d);
    float4 db = *(const float4*)(decay_bias + d);
    float4 a, s;
    a.x = 1.f / (1.f + expf(-(ap.x + db.x)));
    a.y = 1.f / (1.f + expf(-(ap.y + db.y)));
    a.z = 1.f / (1.f + expf(-(ap.z + db.z)));
    a.w = 1.f / (1.f + expf(-(ap.w + db.w)));
    s.x = sqrtf(fmaxf(1.f - a.x * a.x, 1e-8f)) * (vv.x / (1.f + expf(-ip.x)));
    s.y = sqrtf(fmaxf(1.f - a.y * a.y, 1e-8f)) * (vv.y / (1.f + expf(-ip.y)));
    s.z = sqrtf(fmaxf(1.f - a.z * a.z, 1e-8f)) * (vv.z / (1.f + expf(-ip.z)));
    s.w = sqrtf(fmaxf(1.f - a.w * a.w, 1e-8f)) * (vv.w / (1.f + expf(-ip.w)));
    *(float4*)(g_a + i4) = a;
    *(float4*)(g_s + i4) = s;
}

// ---------------- phase 1: per-chunk stats (exact reference numerics) ----------------
__global__ __launch_bounds__(256) void chunk_stats_kernel()
{
    int d = blockIdx.x * 256 + threadIdx.x;
    int c = blockIdx.y;
    int b = blockIdx.z;
    size_t base = ((size_t)b * SEQ + (size_t)c * CHUNKSZ) * DREC + d;

    float cl = 0.f, cd = 1.f, ws = 0.f;
    #pragma unroll 4
    for (int j = 0; j < CHUNKSZ; j++) {
        float a = g_a[base + (size_t)j * DREC];
        float s = g_s[base + (size_t)j * DREC];
        cl += logf(fmaxf(a, 1e-10f));
        cd  = expf(cl);
        ws += s / fmaxf(cd, 1e-10f);
    }
    int o = (b * NCHUNK + c) * DREC + d;
    g_ctd[o] = cd;
    g_cfs[o] = cd * ws;
}

// ---------------- phase 2: serial inter-chunk scan ----------------
__global__ __launch_bounds__(256) void interchunk_kernel()
{
    int d = blockIdx.x * 256 + threadIdx.x;
    int b = blockIdx.y;
    float cl = 0.f, ccd = 1.f, cw = 0.f;
    for (int c = 0; c < NCHUNK; c++) {
        int o = (b * NCHUNK + c) * DREC + d;
        g_inc[o] = ccd * cw;
        cl += logf(fmaxf(g_ctd[o], 1e-10f));
        ccd = expf(cl);
        cw += g_cfs[o] / fmaxf(ccd, 1e-10f);
    }
}

// ---------------- phase 3: final states -> h hi/lo bf16 ----------------
__global__ __launch_bounds__(256) void states_kernel()
{
    int d0 = (blockIdx.x * 256 + threadIdx.x) * 2;   // 2 channels per thread
    int c  = blockIdx.y;
    int b  = blockIdx.z;
    size_t base = ((size_t)b * SEQ + (size_t)c * CHUNKSZ) * DREC + d0;
    const float2 inc = *(const float2*)(g_inc + (b * NCHUNK + c) * DREC + d0);

    float cl0 = 0.f, ws0 = 0.f, cl1 = 0.f, ws1 = 0.f;
    #pragma unroll 4
    for (int j = 0; j < CHUNKSZ; j++) {
        size_t idx = base + (size_t)j * DREC;
        float2 a = *(const float2*)(g_a + idx);
        float2 s = *(const float2*)(g_s + idx);
        cl0 += logf(fmaxf(a.x, 1e-10f));
        cl1 += logf(fmaxf(a.y, 1e-10f));
        float cd0 = expf(cl0), cd1 = expf(cl1);
        ws0 += s.x / fmaxf(cd0, 1e-10f);
        ws1 += s.y / fmaxf(cd1, 1e-10f);
        float h0 = cd0 * ws0 + cd0 * inc.x;
        float h1 = cd1 * ws1 + cd1 * inc.y;
        __nv_bfloat162 hh = __floats2bfloat162_rn(h0, h1);
        __nv_bfloat162 hl = __floats2bfloat162_rn(h0 - __bfloat162float(hh.x),
                                                  h1 - __bfloat162float(hh.y));
        *(uint32_t*)(g_hh + idx) = *(uint32_t*)&hh;
        *(uint32_t*)(g_hl + idx) = *(uint32_t*)&hl;
    }
}

// ---------------- launcher ----------------
extern "C" void kernel_launch(void* const* d_in, const int* in_sizes, int n_in,
                              void* d_out, int out_size)
{
    const float* x          = (const float*)d_in[0];
    const float* W_aiv      = (const float*)d_in[1];
    const float* decay_bias = (const float*)d_in[2];
    const float* W_mix      = (const float*)d_in[3];
    const float* b_mix      = (const float*)d_in[4];
    float*       out        = (float*)d_out;

    float* aiv_p;
    __nv_bfloat16 *xh, *xl, *hh, *hl, *w1th, *w1tl, *w2th, *w2tl;
    cudaGetSymbolAddress((void**)&aiv_p, g_aiv);
    cudaGetSymbolAddress((void**)&xh,    g_xh);
    cudaGetSymbolAddress((void**)&xl,    g_xl);
    cudaGetSymbolAddress((void**)&hh,    g_hh);
    cudaGetSymbolAddress((void**)&hl,    g_hl);
    cudaGetSymbolAddress((void**)&w1th,  g_w1th);
    cudaGetSymbolAddress((void**)&w1tl,  g_w1tl);
    cudaGetSymbolAddress((void**)&w2th,  g_w2th);
    cudaGetSymbolAddress((void**)&w2tl,  g_w2tl);

    cudaFuncSetAttribute(tc_gemm, cudaFuncAttributeMaxDynamicSharedMemorySize, GEMM_SMEM);

    // input & weight conversion
    split_kernel<<<(MROWS * KDIM) / 1024, 256>>>(x, xh, xl);
    wconv_kernel<<<dim3(3072 / 32, 1024 / 32), 256>>>(W_aiv, w1th, w1tl, 1024, 3072);
    wconv_kernel<<<dim3(1024 / 32, 1024 / 32), 256>>>(W_mix, w2th, w2tl, 1024, 1024);

    // 1) aiv = x @ W_aiv
    tc_gemm<<<dim3(3072 / BN, MROWS / BM), 256, GEMM_SMEM>>>(xh, xl, w1th, w1tl, nullptr, aiv_p, 3072);
    // 2) gates
    act_kernel<<<(MROWS * DREC) / 1024, 256>>>(decay_bias);
    // 3) chunked scan
    chunk_stats_kernel<<<dim3(DREC / 256, NCHUNK, BATCH), 256>>>();
    interchunk_kernel<<<dim3(DREC / 256, BATCH), 256>>>();
    states_kernel<<<dim3(DREC / 512, NCHUNK, BATCH), 256>>>();
    // 4) out = h @ W_mix + b_mix
    tc_gemm<<<dim3(1024 / BN, MROWS / BM), 256, GEMM_SMEM>>>(hh, hl, w2th, w2tl, b_mix, out, 1024);
}